// round 10
// baseline (speedup 1.0000x reference)
#include <cuda_runtime.h>

#define EPS 1e-8f
#define BN 4
#define CN 128
#define HN 256
#define WN 256
#define HW (HN*WN)       // 65536
#define NCH (BN*CN)      // 512
#define MHW (128*128)    // 16384
#define NPART 4
#define APPLY_BLOCKS (32 * NCH)    // 16384

// Scratch: per-channel partial sums, coefficients, sync state (all zero-init;
// every counter/flag is reset in-kernel so graph replays are deterministic).
__device__ float g_sums[NPART * NCH * 12];
__device__ float g_coef[NCH * 4];          // per channel: P, Q, k1, k2
__device__ int   g_cnt[BN];                // per-batch cg-completion count
__device__ volatile int g_flag[BN];        // per-batch coef-ready flag
__device__ unsigned int g_done;            // global block-done counter

__device__ __forceinline__ float warpSum(float v) {
#pragma unroll
    for (int o = 16; o; o >>= 1) v += __shfl_xor_sync(0xffffffffu, v, o);
    return v;
}

__device__ __forceinline__ void gdc_wait() {
    asm volatile("griddepcontrol.wait;" ::: "memory");
}
__device__ __forceinline__ void gdc_launch_dependents() {
    asm volatile("griddepcontrol.launch_dependents;" ::: "memory");
}

// ---------------------------------------------------------------------------
// Kernel 1 (unchanged from R9 measured-good): per-(b,c) partial reductions,
// split by tensor. 6 accumulators, 30 regs, 92% occupancy, 74% DRAM.
//   A = Sum x*m, B = Sum x*m^3, C = Sum x^2*m^4  per region;
// mask 2x2-upsample factoring: sx=sum4(x), sq=sum4(x^2) per mask scalar.
// ---------------------------------------------------------------------------
__global__ __launch_bounds__(256) void k_reduce(const float4* __restrict__ x1,
                                                const float4* __restrict__ x2,
                                                const float* __restrict__ mask) {
    int bid  = blockIdx.x;
    int ch   = bid & (NCH - 1);
    int part = (bid >> 9) & (NPART - 1);
    int tensor = bid >> 11;           // 0 = x1, 1 = x2
    int b  = ch >> 7;
    const float4* p = (tensor ? x2 : x1) + (size_t)ch * (HW / 4) + part * 4096;
    const float*  mb = mask + b * MHW;
    int t = threadIdx.x;
    int lane = t & 31, wid = t >> 5;
    int col = t & 63;
    int rpl0 = t >> 6;

    float a0 = 0.f, a1 = 0.f, a2 = 0.f, a3 = 0.f, a4 = 0.f, a5 = 0.f;

#pragma unroll 1
    for (int k = 0; k < 8; k++) {
        int rp = k * 4 + rpl0;
        int q0 = rp * 128 + col;
        float4 xa = __ldcs(p + q0);
        float4 xb = __ldcs(p + q0 + 64);
        int mrow = part * 32 + rp;
        float2 mp = *reinterpret_cast<const float2*>(mb + mrow * 128 + 2 * col);

#pragma unroll
        for (int hsel = 0; hsel < 2; hsel++) {
            float m = hsel ? mp.y : mp.x;
            float e0 = hsel ? xa.z : xa.x, e1 = hsel ? xa.w : xa.y;
            float e2 = hsel ? xb.z : xb.x, e3 = hsel ? xb.w : xb.y;

            float om = 1.0f - m;
            float m2 = m * m, om2 = om * om;

            float sx = (e0 + e1) + (e2 + e3);
            float sq = fmaf(e0, e0, fmaf(e1, e1, fmaf(e2, e2, e3 * e3)));
            a0 = fmaf(sx, m, a0);
            a1 = fmaf(sx * m, m2, a1);
            a2 = fmaf(sq, m2 * m2, a2);
            a3 = fmaf(sx, om, a3);
            a4 = fmaf(sx * om, om2, a4);
            a5 = fmaf(sq, om2 * om2, a5);
        }
    }

    float vals[6] = {a0, a1, a2, a3, a4, a5};
    __shared__ float red[6][8];
#pragma unroll
    for (int i = 0; i < 6; i++) {
        float s = warpSum(vals[i]);
        if (lane == 0) red[i][wid] = s;
    }
    __syncthreads();
    if (wid == 0) {
#pragma unroll
        for (int i = 0; i < 6; i++) {
            float s = (lane < 8) ? red[i][lane] : 0.f;
            s = warpSum(s);
            if (lane == 0)
                g_sums[(size_t)(part * NCH + ch) * 12 + tensor * 6 + i] = s;
        }
    }
    __threadfence();
    __syncthreads();
    gdc_launch_dependents();
}

// ---------------------------------------------------------------------------
// Kernel 2: apply WITH integrated stats. Blocks flat<16 (wave-1 resident by
// CLC bid order) gdc_wait on reduce, compute stats + GEMV for (b, cg),
// publish coef quarter, release per-batch flag. ALL blocks pre-issue their
// x1/mask loads at launch (no dependence on reduce), spin on flag[b]
// (thread 0 + syncthreads), then compute/store:
//   out = x1*(m^2*P + om^2*Q) + k1*m + k2*om
// Self-resetting sync state via global done-counter (graph replay safe).
// ---------------------------------------------------------------------------
__global__ __launch_bounds__(256) void k_apply(const float4* __restrict__ x1,
                                               const float* __restrict__ mask,
                                               float4* __restrict__ out,
                                               const float* __restrict__ w_in_mean,
                                               const float* __restrict__ w_in_var,
                                               const float* __restrict__ w_out_mean,
                                               const float* __restrict__ w_out_var) {
    int bx = blockIdx.x;              // spatial chunk 0..31
    int ch = blockIdx.y;              // channel 0..511
    int flat = ch * 32 + bx;          // CLC launch order: flat 0..15 in wave 1
    int b = ch >> 7;
    int t = threadIdx.x;
    int lane = t & 31, wid = t >> 5;

    const float* mb = mask + b * MHW;
    const float4* px = x1 + (size_t)ch * (HW / 4);
    float4* po = out + (size_t)ch * (HW / 4);
    int q0 = bx * 512 + t;
    int q1 = q0 + 256;

    // ---- pre-issue independent loads (input-only; no reduce dependence) ----
    float4 v0 = px[q0];
    float4 v1 = px[q1];
    int mi0 = ((q0 >> 7) << 7) | ((2 * q0) & 126);
    int mi1 = ((q1 >> 7) << 7) | ((2 * q1) & 126);
    float2 mp0 = *reinterpret_cast<const float2*>(mb + mi0);
    float2 mp1 = *reinterpret_cast<const float2*>(mb + mi1);

    // ---- stats blocks: flat 0..15 -> (sb, cg) ----
    if (flat < 4 * BN) {
        int sb = flat >> 2;           // batch this stats block serves
        int cg = flat & 3;            // channel row-group [cg*32, cg*32+32)
        const float* smb = mask + sb * MHW;

        __shared__ float sred[2][8];
        __shared__ float ssum[CN * 12];
        __shared__ float v_sh[4 * 256];
        __shared__ float mr_sh[512];
        __shared__ float ada_sh[128];
        __shared__ float sh_nin, sh_nout, sh_M2, sh_M2o;

        // mask sums (input-only, overlaps reduce drain; exact 2x2 upsample)
        {
            float s1 = 0, s2 = 0;
            for (int i = t; i < MHW; i += 256) { float m = smb[i]; s1 += m; s2 += m * m; }
            s1 = warpSum(s1); s2 = warpSum(s2);
            if (lane == 0) { sred[0][wid] = s1; sred[1][wid] = s2; }
        }
        __syncthreads();
        if (t == 0) {
            float S1 = 0, S2 = 0;
            for (int i = 0; i < 8; i++) { S1 += sred[0][i]; S2 += sred[1][i]; }
            float msum = 4.f * S1, m2sum = 4.f * S2;
            sh_nin  = msum + EPS;
            sh_nout = ((float)HW - msum) + EPS;
            sh_M2   = m2sum;
            sh_M2o  = (float)HW - 2.f * msum + m2sum;
        }

        gdc_wait();                    // now need g_sums from k_reduce

        for (int id = t; id < CN * 12; id += 256) {
            int c = id / 12, i = id - c * 12;
            float v = 0.f;
#pragma unroll
            for (int p = 0; p < NPART; p++)
                v += g_sums[(size_t)(p * NCH + sb * CN + c) * 12 + i];
            ssum[id] = v;
        }
        __syncthreads();

        {
            int c = t & 127;
            int isx2 = t >> 7;
            const float* s = ssum + c * 12 + isx2 * 6;
            float A = s[0], Bb = s[1], Cc = s[2], Ao = s[3], Bo = s[4], Co = s[5];
            float mean_in = A / sh_nin;
            float var_in = (Cc - 2.f * mean_in * Bb + mean_in * mean_in * sh_M2) / sh_nin;
            var_in = fmaxf(var_in, 0.f);
            float mean_out = Ao / sh_nout;
            float var_out = (Co - 2.f * mean_out * Bo + mean_out * mean_out * sh_M2o) / sh_nout;
            var_out = fmaxf(var_out, 0.f);
            int vi = isx2 * 128 + c;
            v_sh[vi]       = mean_in;
            v_sh[256 + vi] = var_in;
            v_sh[512 + vi] = mean_out;
            v_sh[768 + vi] = var_out;
            if (!isx2) {
                mr_sh[c]       = mean_in;
                mr_sh[128 + c] = rsqrtf(var_in + EPS);
                mr_sh[256 + c] = mean_out;
                mr_sh[384 + c] = rsqrtf(var_out + EPS);
            }
        }
        __syncthreads();

        {
            const float* wmats[4] = {w_in_mean, w_in_var, w_out_mean, w_out_var};
#pragma unroll
            for (int it = 0; it < 16; it++) {
                int task = wid * 16 + it;      // mat*32 + lr
                int mat = task >> 5, lr = task & 31;
                const float* wrow = wmats[mat] + (size_t)(cg * 32 + lr) * 256;
                const float* vv = v_sh + mat * 256;
                float a = 0.f;
#pragma unroll
                for (int j = 0; j < 8; j++)
                    a = fmaf(__ldg(wrow + lane + 32 * j), vv[lane + 32 * j], a);
                a = warpSum(a);
                if (lane == 0) ada_sh[task] = a;
            }
        }
        __syncthreads();

        if (t < 32) {
            int c = cg * 32 + t;
            float mu_i = mr_sh[c], r_i = mr_sh[128 + c];
            float mu_o = mr_sh[256 + c], r_o = mr_sh[384 + c];
            float P  = r_i * ada_sh[32 + t];
            float Q  = r_o * ada_sh[96 + t];
            float k1 = ada_sh[t]      - mu_i * P;
            float k2 = ada_sh[64 + t] - mu_o * Q;
            reinterpret_cast<float4*>(g_coef)[sb * CN + c] = make_float4(P, Q, k1, k2);
        }
        __threadfence();               // release coef quarter
        __syncthreads();
        if (t == 0) {
            int v = atomicAdd(&g_cnt[sb], 1);
            if (v == 3) {              // all 4 cg quarters published
                g_cnt[sb] = 0;         // reset for next replay (no more readers)
                __threadfence();
                g_flag[sb] = 1;        // release
            }
        }
    }

    // ---- wait for this batch's coefficients ----
    __shared__ int s_ready;
    if (t == 0) {
        while (g_flag[b] == 0) { __nanosleep(64); }
        __threadfence();               // acquire
        s_ready = 1;
    }
    __syncthreads();
    (void)s_ready;

    float4 coef = reinterpret_cast<const float4*>(g_coef)[ch];
    float P = coef.x, Q = coef.y, k1 = coef.z, k2 = coef.w;

#pragma unroll
    for (int r = 0; r < 2; r++) {
        int q = r ? q1 : q0;
        float4 v = r ? v1 : v0;
        float2 mp = r ? mp1 : mp0;
        float xs[4] = {v.x, v.y, v.z, v.w};
        float ms[4] = {mp.x, mp.x, mp.y, mp.y};
        float os[4];
#pragma unroll
        for (int i = 0; i < 4; i++) {
            float m = ms[i], om = 1.f - m;
            float s = m * m * P + om * om * Q;
            os[i] = xs[i] * s + k1 * m + k2 * om;
        }
        po[q] = make_float4(os[0], os[1], os[2], os[3]);
    }

    // ---- replay-safe reset: last finishing block clears flags ----
    __syncthreads();
    if (t == 0) {
        unsigned int v = atomicAdd(&g_done, 1u);
        if (v == (unsigned)(APPLY_BLOCKS - 1)) {
            g_flag[0] = 0; g_flag[1] = 0; g_flag[2] = 0; g_flag[3] = 0;
            g_done = 0u;
        }
    }
}

extern "C" void kernel_launch(void* const* d_in, const int* in_sizes, int n_in,
                              void* d_out, int out_size) {
    const float* x1         = (const float*)d_in[0];
    const float* x2         = (const float*)d_in[1];
    const float* mask       = (const float*)d_in[2];
    const float* w_in_mean  = (const float*)d_in[3];
    const float* w_in_var   = (const float*)d_in[4];
    const float* w_out_mean = (const float*)d_in[5];
    const float* w_out_var  = (const float*)d_in[6];
    float* out = (float*)d_out;

    // 1) reduce — plain launch, tensor-split grid
    k_reduce<<<2 * NPART * NCH, 256>>>((const float4*)x1, (const float4*)x2, mask);

    // 2) apply+stats — PDL consumer of reduce
    {
        cudaLaunchConfig_t cfg = {};
        cfg.gridDim = dim3(32, NCH);
        cfg.blockDim = dim3(256);
        cudaLaunchAttribute attr[1];
        attr[0].id = cudaLaunchAttributeProgrammaticStreamSerialization;
        attr[0].val.programmaticStreamSerializationAllowed = 1;
        cfg.attrs = attr;
        cfg.numAttrs = 1;
        cudaLaunchKernelEx(&cfg, k_apply, (const float4*)x1, mask, (float4*)out,
                           w_in_mean, w_in_var, w_out_mean, w_out_var);
    }
}

// round 11
// speedup vs baseline: 1.0255x; 1.0255x over previous
#include <cuda_runtime.h>

#define EPS 1e-8f
#define BN 4
#define CN 128
#define HN 256
#define WN 256
#define HW (HN*WN)       // 65536
#define NCH (BN*CN)      // 512
#define MHW (128*128)    // 16384
#define NPART 4

// Scratch. All sync state is reset in-kernel each launch sequence:
// k_reduce bid0 clears g_flag at its start (stream-ordered: prior apply has
// fully completed; this launch's apply starts only after reduce's PDL fire).
// g_cnt self-resets (the 4th arrival zeroes it before setting the flag).
__device__ float g_sums[NPART * NCH * 12];
__device__ float g_coef[NCH * 4];          // per channel: P, Q, k1, k2
__device__ int   g_cnt[BN];                // per-batch cg-completion count
__device__ volatile int g_flag[BN];        // per-batch coef-ready flag

__device__ __forceinline__ float warpSum(float v) {
#pragma unroll
    for (int o = 16; o; o >>= 1) v += __shfl_xor_sync(0xffffffffu, v, o);
    return v;
}

__device__ __forceinline__ void gdc_wait() {
    asm volatile("griddepcontrol.wait;" ::: "memory");
}
__device__ __forceinline__ void gdc_launch_dependents() {
    asm volatile("griddepcontrol.launch_dependents;" ::: "memory");
}

// ---------------------------------------------------------------------------
// Kernel 1 (R9 measured-good body): per-(b,c) partial reductions, split by
// tensor. 6 accumulators, 30 regs, 92% occ, 74% DRAM.
//   A = Sum x*m, B = Sum x*m^3, C = Sum x^2*m^4  per region;
// mask 2x2-upsample factoring: sx=sum4(x), sq=sum4(x^2) per mask scalar.
// NEW: bid 0 clears the apply-flags at start (replay-safe reset, no atomics).
// ---------------------------------------------------------------------------
__global__ __launch_bounds__(256) void k_reduce(const float4* __restrict__ x1,
                                                const float4* __restrict__ x2,
                                                const float* __restrict__ mask) {
    int bid  = blockIdx.x;
    if (bid == 0 && threadIdx.x < BN) g_flag[threadIdx.x] = 0;

    int ch   = bid & (NCH - 1);
    int part = (bid >> 9) & (NPART - 1);
    int tensor = bid >> 11;           // 0 = x1, 1 = x2
    int b  = ch >> 7;
    const float4* p = (tensor ? x2 : x1) + (size_t)ch * (HW / 4) + part * 4096;
    const float*  mb = mask + b * MHW;
    int t = threadIdx.x;
    int lane = t & 31, wid = t >> 5;
    int col = t & 63;
    int rpl0 = t >> 6;

    float a0 = 0.f, a1 = 0.f, a2 = 0.f, a3 = 0.f, a4 = 0.f, a5 = 0.f;

#pragma unroll 1
    for (int k = 0; k < 8; k++) {
        int rp = k * 4 + rpl0;
        int q0 = rp * 128 + col;
        float4 xa = __ldcs(p + q0);
        float4 xb = __ldcs(p + q0 + 64);
        int mrow = part * 32 + rp;
        float2 mp = *reinterpret_cast<const float2*>(mb + mrow * 128 + 2 * col);

#pragma unroll
        for (int hsel = 0; hsel < 2; hsel++) {
            float m = hsel ? mp.y : mp.x;
            float e0 = hsel ? xa.z : xa.x, e1 = hsel ? xa.w : xa.y;
            float e2 = hsel ? xb.z : xb.x, e3 = hsel ? xb.w : xb.y;

            float om = 1.0f - m;
            float m2 = m * m, om2 = om * om;

            float sx = (e0 + e1) + (e2 + e3);
            float sq = fmaf(e0, e0, fmaf(e1, e1, fmaf(e2, e2, e3 * e3)));
            a0 = fmaf(sx, m, a0);
            a1 = fmaf(sx * m, m2, a1);
            a2 = fmaf(sq, m2 * m2, a2);
            a3 = fmaf(sx, om, a3);
            a4 = fmaf(sx * om, om2, a4);
            a5 = fmaf(sq, om2 * om2, a5);
        }
    }

    float vals[6] = {a0, a1, a2, a3, a4, a5};
    __shared__ float red[6][8];
#pragma unroll
    for (int i = 0; i < 6; i++) {
        float s = warpSum(vals[i]);
        if (lane == 0) red[i][wid] = s;
    }
    __syncthreads();
    if (wid == 0) {
#pragma unroll
        for (int i = 0; i < 6; i++) {
            float s = (lane < 8) ? red[i][lane] : 0.f;
            s = warpSum(s);
            if (lane == 0)
                g_sums[(size_t)(part * NCH + ch) * 12 + tensor * 6 + i] = s;
        }
    }
    __threadfence();
    __syncthreads();
    gdc_launch_dependents();
}

// ---------------------------------------------------------------------------
// Kernel 2: apply with integrated stats. Blocks flat<16 (wave-1 resident by
// bid order) do mask sums pre-gdc_wait, then stats + GEMV for (sb, cg),
// publish coef quarter, 4th arrival sets g_flag[sb]. All blocks pre-issue
// their x1/mask loads, spin on g_flag[b] (read-only polling — no atomics),
// then:  out = x1*(m^2*P + om^2*Q) + k1*m + k2*om
// NO per-block global atomics at drain (R10's 16K-atomic reset cost ~36us).
// ---------------------------------------------------------------------------
__global__ __launch_bounds__(256) void k_apply(const float4* __restrict__ x1,
                                               const float* __restrict__ mask,
                                               float4* __restrict__ out,
                                               const float* __restrict__ w_in_mean,
                                               const float* __restrict__ w_in_var,
                                               const float* __restrict__ w_out_mean,
                                               const float* __restrict__ w_out_var) {
    int bx = blockIdx.x;              // spatial chunk 0..31
    int ch = blockIdx.y;              // channel 0..511
    int flat = ch * 32 + bx;          // HW linear bid; 0..15 are wave-1
    int b = ch >> 7;
    int t = threadIdx.x;
    int lane = t & 31, wid = t >> 5;

    const float* mb = mask + b * MHW;
    const float4* px = x1 + (size_t)ch * (HW / 4);
    float4* po = out + (size_t)ch * (HW / 4);
    int q0 = bx * 512 + t;
    int q1 = q0 + 256;

    // ---- pre-issue independent loads ----
    float4 v0 = px[q0];
    float4 v1 = px[q1];
    int mi0 = ((q0 >> 7) << 7) | ((2 * q0) & 126);
    int mi1 = ((q1 >> 7) << 7) | ((2 * q1) & 126);
    float2 mp0 = *reinterpret_cast<const float2*>(mb + mi0);
    float2 mp1 = *reinterpret_cast<const float2*>(mb + mi1);

    // ---- stats blocks: flat 0..15 -> (sb, cg) ----
    if (flat < 4 * BN) {
        int sb = flat >> 2;           // batch this stats block serves
        int cg = flat & 3;            // channel row-group [cg*32, cg*32+32)
        const float* smb = mask + sb * MHW;

        __shared__ float sred[2][8];
        __shared__ float ssum[CN * 12];
        __shared__ float v_sh[4 * 256];
        __shared__ float mr_sh[512];
        __shared__ float ada_sh[128];
        __shared__ float sh_nin, sh_nout, sh_M2, sh_M2o;

        // mask sums (input-only; exact 2x2-repeat upsample)
        {
            float s1 = 0, s2 = 0;
            for (int i = t; i < MHW; i += 256) { float m = smb[i]; s1 += m; s2 += m * m; }
            s1 = warpSum(s1); s2 = warpSum(s2);
            if (lane == 0) { sred[0][wid] = s1; sred[1][wid] = s2; }
        }
        __syncthreads();
        if (t == 0) {
            float S1 = 0, S2 = 0;
            for (int i = 0; i < 8; i++) { S1 += sred[0][i]; S2 += sred[1][i]; }
            float msum = 4.f * S1, m2sum = 4.f * S2;
            sh_nin  = msum + EPS;
            sh_nout = ((float)HW - msum) + EPS;
            sh_M2   = m2sum;
            sh_M2o  = (float)HW - 2.f * msum + m2sum;
        }

        gdc_wait();                    // need g_sums from k_reduce

        for (int id = t; id < CN * 12; id += 256) {
            int c = id / 12, i = id - c * 12;
            float v = 0.f;
#pragma unroll
            for (int p = 0; p < NPART; p++)
                v += g_sums[(size_t)(p * NCH + sb * CN + c) * 12 + i];
            ssum[id] = v;
        }
        __syncthreads();

        {
            int c = t & 127;
            int isx2 = t >> 7;
            const float* s = ssum + c * 12 + isx2 * 6;
            float A = s[0], Bb = s[1], Cc = s[2], Ao = s[3], Bo = s[4], Co = s[5];
            float mean_in = A / sh_nin;
            float var_in = (Cc - 2.f * mean_in * Bb + mean_in * mean_in * sh_M2) / sh_nin;
            var_in = fmaxf(var_in, 0.f);
            float mean_out = Ao / sh_nout;
            float var_out = (Co - 2.f * mean_out * Bo + mean_out * mean_out * sh_M2o) / sh_nout;
            var_out = fmaxf(var_out, 0.f);
            int vi = isx2 * 128 + c;
            v_sh[vi]       = mean_in;
            v_sh[256 + vi] = var_in;
            v_sh[512 + vi] = mean_out;
            v_sh[768 + vi] = var_out;
            if (!isx2) {
                mr_sh[c]       = mean_in;
                mr_sh[128 + c] = rsqrtf(var_in + EPS);
                mr_sh[256 + c] = mean_out;
                mr_sh[384 + c] = rsqrtf(var_out + EPS);
            }
        }
        __syncthreads();

        {
            const float* wmats[4] = {w_in_mean, w_in_var, w_out_mean, w_out_var};
#pragma unroll
            for (int it = 0; it < 16; it++) {
                int task = wid * 16 + it;      // mat*32 + lr
                int mat = task >> 5, lr = task & 31;
                const float* wrow = wmats[mat] + (size_t)(cg * 32 + lr) * 256;
                const float* vv = v_sh + mat * 256;
                float a = 0.f;
#pragma unroll
                for (int j = 0; j < 8; j++)
                    a = fmaf(__ldg(wrow + lane + 32 * j), vv[lane + 32 * j], a);
                a = warpSum(a);
                if (lane == 0) ada_sh[task] = a;
            }
        }
        __syncthreads();

        if (t < 32) {
            int c = cg * 32 + t;
            float mu_i = mr_sh[c], r_i = mr_sh[128 + c];
            float mu_o = mr_sh[256 + c], r_o = mr_sh[384 + c];
            float P  = r_i * ada_sh[32 + t];
            float Q  = r_o * ada_sh[96 + t];
            float k1 = ada_sh[t]      - mu_i * P;
            float k2 = ada_sh[64 + t] - mu_o * Q;
            reinterpret_cast<float4*>(g_coef)[sb * CN + c] = make_float4(P, Q, k1, k2);
        }
        __threadfence();               // release coef quarter
        __syncthreads();
        if (t == 0) {
            int v = atomicAdd(&g_cnt[sb], 1);   // 16 atomics total, 4 addrs
            if (v == 3) {
                g_cnt[sb] = 0;         // self-reset (no more readers this run)
                __threadfence();
                g_flag[sb] = 1;        // release
            }
        }
    }

    // ---- wait for this batch's coefficients (read-only polling) ----
    __shared__ int s_ready;
    if (t == 0) {
        while (g_flag[b] == 0) { __nanosleep(64); }
        __threadfence();               // acquire
        s_ready = 1;
    }
    __syncthreads();
    (void)s_ready;

    float4 coef = reinterpret_cast<const float4*>(g_coef)[ch];
    float P = coef.x, Q = coef.y, k1 = coef.z, k2 = coef.w;

#pragma unroll
    for (int r = 0; r < 2; r++) {
        int q = r ? q1 : q0;
        float4 v = r ? v1 : v0;
        float2 mp = r ? mp1 : mp0;
        float xs[4] = {v.x, v.y, v.z, v.w};
        float ms[4] = {mp.x, mp.x, mp.y, mp.y};
        float os[4];
#pragma unroll
        for (int i = 0; i < 4; i++) {
            float m = ms[i], om = 1.f - m;
            float s = m * m * P + om * om * Q;
            os[i] = xs[i] * s + k1 * m + k2 * om;
        }
        po[q] = make_float4(os[0], os[1], os[2], os[3]);
    }
    // no drain-side sync state: flags are cleared by next launch's k_reduce
}

extern "C" void kernel_launch(void* const* d_in, const int* in_sizes, int n_in,
                              void* d_out, int out_size) {
    const float* x1         = (const float*)d_in[0];
    const float* x2         = (const float*)d_in[1];
    const float* mask       = (const float*)d_in[2];
    const float* w_in_mean  = (const float*)d_in[3];
    const float* w_in_var   = (const float*)d_in[4];
    const float* w_out_mean = (const float*)d_in[5];
    const float* w_out_var  = (const float*)d_in[6];
    float* out = (float*)d_out;

    // 1) reduce — plain launch (stream-ordered after any prior apply, so its
    //    bid0 flag-clear is race-free), tensor-split grid
    k_reduce<<<2 * NPART * NCH, 256>>>((const float4*)x1, (const float4*)x2, mask);

    // 2) apply+stats — PDL consumer of reduce
    {
        cudaLaunchConfig_t cfg = {};
        cfg.gridDim = dim3(32, NCH);
        cfg.blockDim = dim3(256);
        cudaLaunchAttribute attr[1];
        attr[0].id = cudaLaunchAttributeProgrammaticStreamSerialization;
        attr[0].val.programmaticStreamSerializationAllowed = 1;
        cfg.attrs = attr;
        cfg.numAttrs = 1;
        cudaLaunchKernelEx(&cfg, k_apply, (const float4*)x1, mask, (float4*)out,
                           w_in_mean, w_in_var, w_out_mean, w_out_var);
    }
}

// round 12
// speedup vs baseline: 1.2271x; 1.1966x over previous
#include <cuda_runtime.h>

#define EPS 1e-8f
#define BN 4
#define CN 128
#define HN 256
#define WN 256
#define HW (HN*WN)       // 65536
#define NCH (BN*CN)      // 512
#define MHW (128*128)    // 16384
#define NPART 4

// Scratch: per-channel partial sums (NPART parts) + final coefficients.
__device__ float g_sums[NPART * NCH * 12];
__device__ float g_coef[NCH * 4];          // per channel: P, Q, k1, k2

__device__ __forceinline__ float warpSum(float v) {
#pragma unroll
    for (int o = 16; o; o >>= 1) v += __shfl_xor_sync(0xffffffffu, v, o);
    return v;
}

__device__ __forceinline__ void gdc_wait() {
    asm volatile("griddepcontrol.wait;" ::: "memory");
}
__device__ __forceinline__ void gdc_launch_dependents() {
    asm volatile("griddepcontrol.launch_dependents;" ::: "memory");
}

// ---------------------------------------------------------------------------
// Kernel 1 (R9 measured-good, unchanged): per-(b,c) partial reductions,
// split by tensor. 6 accumulators, 30 regs, 92% occ, 74% DRAM, 46.3us.
//   A = Sum x*m, B = Sum x*m^3, C = Sum x^2*m^4  per region;
// mask 2x2-upsample factoring: sx=sum4(x), sq=sum4(x^2) per mask scalar.
// ---------------------------------------------------------------------------
__global__ __launch_bounds__(256) void k_reduce(const float4* __restrict__ x1,
                                                const float4* __restrict__ x2,
                                                const float* __restrict__ mask) {
    int bid  = blockIdx.x;
    int ch   = bid & (NCH - 1);
    int part = (bid >> 9) & (NPART - 1);
    int tensor = bid >> 11;           // 0 = x1, 1 = x2
    int b  = ch >> 7;
    const float4* p = (tensor ? x2 : x1) + (size_t)ch * (HW / 4) + part * 4096;
    const float*  mb = mask + b * MHW;
    int t = threadIdx.x;
    int lane = t & 31, wid = t >> 5;
    int col = t & 63;
    int rpl0 = t >> 6;

    float a0 = 0.f, a1 = 0.f, a2 = 0.f, a3 = 0.f, a4 = 0.f, a5 = 0.f;

#pragma unroll 1
    for (int k = 0; k < 8; k++) {
        int rp = k * 4 + rpl0;
        int q0 = rp * 128 + col;
        float4 xa = __ldcs(p + q0);
        float4 xb = __ldcs(p + q0 + 64);
        int mrow = part * 32 + rp;
        float2 mp = *reinterpret_cast<const float2*>(mb + mrow * 128 + 2 * col);

#pragma unroll
        for (int hsel = 0; hsel < 2; hsel++) {
            float m = hsel ? mp.y : mp.x;
            float e0 = hsel ? xa.z : xa.x, e1 = hsel ? xa.w : xa.y;
            float e2 = hsel ? xb.z : xb.x, e3 = hsel ? xb.w : xb.y;

            float om = 1.0f - m;
            float m2 = m * m, om2 = om * om;

            float sx = (e0 + e1) + (e2 + e3);
            float sq = fmaf(e0, e0, fmaf(e1, e1, fmaf(e2, e2, e3 * e3)));
            a0 = fmaf(sx, m, a0);
            a1 = fmaf(sx * m, m2, a1);
            a2 = fmaf(sq, m2 * m2, a2);
            a3 = fmaf(sx, om, a3);
            a4 = fmaf(sx * om, om2, a4);
            a5 = fmaf(sq, om2 * om2, a5);
        }
    }

    float vals[6] = {a0, a1, a2, a3, a4, a5};
    __shared__ float red[6][8];
#pragma unroll
    for (int i = 0; i < 6; i++) {
        float s = warpSum(vals[i]);
        if (lane == 0) red[i][wid] = s;
    }
    __syncthreads();
    if (wid == 0) {
#pragma unroll
        for (int i = 0; i < 6; i++) {
            float s = (lane < 8) ? red[i][lane] : 0.f;
            s = warpSum(s);
            if (lane == 0)
                g_sums[(size_t)(part * NCH + ch) * 12 + tensor * 6 + i] = s;
        }
    }
    __threadfence();
    __syncthreads();
    gdc_launch_dependents();
}

// ---------------------------------------------------------------------------
// Kernel 2: stats + modulation GEMVs, rebuilt for critical-path latency.
// grid (BN, 16): 64 blocks, each owns 8 channels (rows rg*8..rg*8+7).
// PRE-WAIT (independent of reduce): (a) this block's 4x8 weight rows ->
// smem (32KB), (b) per-batch mask sums. POST-WAIT (short!): combine g_sums,
// per-channel stats, GEMV entirely from smem, write coef slice.
//   out = x1*(m^2*P + om^2*Q) + k1*m + k2*om
// ---------------------------------------------------------------------------
__global__ __launch_bounds__(256) void k_small(const float* __restrict__ mask,
                                               const float* __restrict__ w_in_mean,
                                               const float* __restrict__ w_in_var,
                                               const float* __restrict__ w_out_mean,
                                               const float* __restrict__ w_out_var) {
    int b  = blockIdx.x;
    int rg = blockIdx.y;              // 8-row group: rows [rg*8, rg*8+8)
    int t = threadIdx.x;
    int lane = t & 31, wid = t >> 5;

    __shared__ float w_sh[4][8][256]; // 32KB: [mat][local_row][j]
    __shared__ float ssum[CN * 12];   // 6KB
    __shared__ float v_sh[4 * 256];   // 4KB: GEMV input vectors per matrix
    __shared__ float ada_sh[32];      // [mat*8 + local_row]
    __shared__ float sred[2][8];
    __shared__ float sh_nin, sh_nout, sh_M2, sh_M2o;

    // ---- PRE-WAIT: weight prefetch (pure input; off the critical path) ----
    {
        const float* wmats[4] = {w_in_mean, w_in_var, w_out_mean, w_out_var};
#pragma unroll
        for (int it = 0; it < 8; it++) {
            int id = t + it * 256;            // 2048 float4 total
            int mat = id >> 9;                // 512 float4 per matrix slice
            int rem = id & 511;
            int row = rem >> 6;               // 64 float4 per row
            int j4  = rem & 63;
            reinterpret_cast<float4*>(&w_sh[mat][row][0])[j4] =
                reinterpret_cast<const float4*>(wmats[mat] + (size_t)(rg * 8 + row) * 256)[j4];
        }
    }

    // ---- PRE-WAIT: mask sums (exact: 2x2-repeat upsample) ----
    const float* mb = mask + b * MHW;
    {
        float s1 = 0, s2 = 0;
        for (int i = t; i < MHW; i += 256) { float m = mb[i]; s1 += m; s2 += m * m; }
        s1 = warpSum(s1); s2 = warpSum(s2);
        if (lane == 0) { sred[0][wid] = s1; sred[1][wid] = s2; }
    }
    __syncthreads();
    if (t == 0) {
        float S1 = 0, S2 = 0;
        for (int i = 0; i < 8; i++) { S1 += sred[0][i]; S2 += sred[1][i]; }
        float msum = 4.f * S1, m2sum = 4.f * S2;
        sh_nin  = msum + EPS;
        sh_nout = ((float)HW - msum) + EPS;
        sh_M2   = m2sum;
        sh_M2o  = (float)HW - 2.f * msum + m2sum;  // Sum (1-m)^2
    }

    // ---- wait for k_reduce's g_sums ----
    gdc_wait();

    // combine the NPART partial sums for this batch
    for (int id = t; id < CN * 12; id += 256) {
        int c = id / 12, i = id - c * 12;
        float v = 0.f;
#pragma unroll
        for (int p = 0; p < NPART; p++)
            v += g_sums[(size_t)(p * NCH + b * CN + c) * 12 + i];
        ssum[id] = v;
    }
    __syncthreads();

    // per-channel stats -> GEMV input vectors
    // v_sh layout: [0..255]=means_in(x1||x2), [256..511]=vars_in,
    //              [512..767]=means_out,      [768..1023]=vars_out
    {
        int c = t & 127;
        int isx2 = t >> 7;
        const float* s = ssum + c * 12 + isx2 * 6;
        float A = s[0], Bb = s[1], Cc = s[2], Ao = s[3], Bo = s[4], Co = s[5];
        float mean_in = A / sh_nin;
        float var_in = (Cc - 2.f * mean_in * Bb + mean_in * mean_in * sh_M2) / sh_nin;
        var_in = fmaxf(var_in, 0.f);
        float mean_out = Ao / sh_nout;
        float var_out = (Co - 2.f * mean_out * Bo + mean_out * mean_out * sh_M2o) / sh_nout;
        var_out = fmaxf(var_out, 0.f);
        int vi = isx2 * 128 + c;
        v_sh[vi]       = mean_in;
        v_sh[256 + vi] = var_in;
        v_sh[512 + vi] = mean_out;
        v_sh[768 + vi] = var_out;
    }
    __syncthreads();

    // GEMV from smem: 32 tasks (mat*8 + local_row), 8 warps x 4 tasks.
    {
#pragma unroll
        for (int it = 0; it < 4; it++) {
            int task = wid * 4 + it;
            int mat = task >> 3, lr = task & 7;
            const float* wrow = &w_sh[mat][lr][0];
            const float* vv = v_sh + mat * 256;
            float a = 0.f;
#pragma unroll
            for (int j = 0; j < 8; j++)
                a = fmaf(wrow[lane + 32 * j], vv[lane + 32 * j], a);
            a = warpSum(a);
            if (lane == 0) ada_sh[task] = a;
        }
    }
    __syncthreads();

    // coefficients for this block's 8 channels
    if (t < 8) {
        int c = rg * 8 + t;
        float mu_i = v_sh[c],       r_i = rsqrtf(v_sh[256 + c] + EPS);
        float mu_o = v_sh[512 + c], r_o = rsqrtf(v_sh[768 + c] + EPS);
        float P  = r_i * ada_sh[8 + t];           // in_var
        float Q  = r_o * ada_sh[24 + t];          // out_var
        float k1 = ada_sh[t]      - mu_i * P;     // in_mean
        float k2 = ada_sh[16 + t] - mu_o * Q;     // out_mean
        reinterpret_cast<float4*>(g_coef)[b * CN + c] = make_float4(P, Q, k1, k2);
    }
    __threadfence();
    __syncthreads();
    gdc_launch_dependents();
}

// ---------------------------------------------------------------------------
// Kernel 3 (R9 measured-good, unchanged): elementwise apply. PRE-WAIT:
// x1 + mask loads; POST-WAIT: read g_coef, compute, store.
// out = x1*(m^2*P + om^2*Q) + k1*m + k2*om
// ---------------------------------------------------------------------------
__global__ __launch_bounds__(256) void k_apply(const float4* __restrict__ x1,
                                               const float* __restrict__ mask,
                                               float4* __restrict__ out) {
    int ch = blockIdx.y;
    int b = ch >> 7;
    const float* mb = mask + b * MHW;
    const float4* px = x1 + (size_t)ch * (HW / 4);
    float4* po = out + (size_t)ch * (HW / 4);
    int q0 = blockIdx.x * 512 + threadIdx.x;

    // pre-wait independent loads
    float4 v0 = px[q0];
    float4 v1 = px[q0 + 256];
    int mi0 = ((q0 >> 7) << 7) | ((2 * q0) & 126);
    int q1 = q0 + 256;
    int mi1 = ((q1 >> 7) << 7) | ((2 * q1) & 126);
    float2 mp0 = *reinterpret_cast<const float2*>(mb + mi0);
    float2 mp1 = *reinterpret_cast<const float2*>(mb + mi1);

    gdc_wait();

    float4 coef = __ldg(&reinterpret_cast<const float4*>(g_coef)[ch]);
    float P = coef.x, Q = coef.y, k1 = coef.z, k2 = coef.w;

#pragma unroll
    for (int r = 0; r < 2; r++) {
        int q = r ? q1 : q0;
        float4 v = r ? v1 : v0;
        float2 mp = r ? mp1 : mp0;
        float xs[4] = {v.x, v.y, v.z, v.w};
        float ms[4] = {mp.x, mp.x, mp.y, mp.y};
        float os[4];
#pragma unroll
        for (int i = 0; i < 4; i++) {
            float m = ms[i], om = 1.f - m;
            float s = m * m * P + om * om * Q;
            os[i] = xs[i] * s + k1 * m + k2 * om;
        }
        po[q] = make_float4(os[0], os[1], os[2], os[3]);
    }
}

extern "C" void kernel_launch(void* const* d_in, const int* in_sizes, int n_in,
                              void* d_out, int out_size) {
    const float* x1         = (const float*)d_in[0];
    const float* x2         = (const float*)d_in[1];
    const float* mask       = (const float*)d_in[2];
    const float* w_in_mean  = (const float*)d_in[3];
    const float* w_in_var   = (const float*)d_in[4];
    const float* w_out_mean = (const float*)d_in[5];
    const float* w_out_var  = (const float*)d_in[6];
    float* out = (float*)d_out;

    // 1) reduce — plain launch, tensor-split grid
    k_reduce<<<2 * NPART * NCH, 256>>>((const float4*)x1, (const float4*)x2, mask);

    // 2) stats+gemv — PDL consumer of reduce (64 blocks, weights prefetched)
    {
        cudaLaunchConfig_t cfg = {};
        cfg.gridDim = dim3(BN, 16);
        cfg.blockDim = dim3(256);
        cudaLaunchAttribute attr[1];
        attr[0].id = cudaLaunchAttributeProgrammaticStreamSerialization;
        attr[0].val.programmaticStreamSerializationAllowed = 1;
        cfg.attrs = attr;
        cfg.numAttrs = 1;
        cudaLaunchKernelEx(&cfg, k_small, mask, w_in_mean, w_in_var, w_out_mean, w_out_var);
    }

    // 3) apply — PDL consumer of k_small
    {
        cudaLaunchConfig_t cfg = {};
        cfg.gridDim = dim3(HW / 4 / 512, NCH);
        cfg.blockDim = dim3(256);
        cudaLaunchAttribute attr[1];
        attr[0].id = cudaLaunchAttributeProgrammaticStreamSerialization;
        attr[0].val.programmaticStreamSerializationAllowed = 1;
        cfg.attrs = attr;
        cfg.numAttrs = 1;
        cudaLaunchKernelEx(&cfg, k_apply, (const float4*)x1, mask, (float4*)out);
    }
}

// round 13
// speedup vs baseline: 1.2515x; 1.0199x over previous
#include <cuda_runtime.h>

#define EPS 1e-8f
#define BN 4
#define CN 128
#define HN 256
#define WN 256
#define HW (HN*WN)       // 65536
#define NCH (BN*CN)      // 512
#define MHW (128*128)    // 16384
#define NPART 4

// Scratch: per-channel partial sums (NPART parts) + final coefficients.
__device__ float g_sums[NPART * NCH * 12];
__device__ float g_coef[NCH * 4];          // per channel: P, Q, k1, k2

__device__ __forceinline__ float warpSum(float v) {
#pragma unroll
    for (int o = 16; o; o >>= 1) v += __shfl_xor_sync(0xffffffffu, v, o);
    return v;
}

__device__ __forceinline__ void gdc_wait() {
    asm volatile("griddepcontrol.wait;" ::: "memory");
}
__device__ __forceinline__ void gdc_launch_dependents() {
    asm volatile("griddepcontrol.launch_dependents;" ::: "memory");
}

// ---------------------------------------------------------------------------
// Kernel 1: per-(b,c) partial reductions, split by tensor (R9 measured-good
// body). CACHE POLICY SPLIT: x1 blocks of batches 2-3 load with DEFAULT
// policy (67MB — fits L2, survives to k_apply which walks in reverse);
// everything else streams __ldcs evict-first. R6 failed because ALL 134MB
// of x1 went default-policy and self-evicted; this is the corrected dose.
//   A = Sum x*m, B = Sum x*m^3, C = Sum x^2*m^4  per region;
// mask 2x2-upsample factoring: sx=sum4(x), sq=sum4(x^2) per mask scalar.
// ---------------------------------------------------------------------------
template<bool STREAM>
__device__ __forceinline__ void reduce_body(const float4* __restrict__ p,
                                            const float* __restrict__ mb,
                                            int part, int t, float* acc) {
    int col = t & 63;
    int rpl0 = t >> 6;
#pragma unroll 1
    for (int k = 0; k < 8; k++) {
        int rp = k * 4 + rpl0;
        int q0 = rp * 128 + col;
        float4 xa = STREAM ? __ldcs(p + q0) : p[q0];
        float4 xb = STREAM ? __ldcs(p + q0 + 64) : p[q0 + 64];
        int mrow = part * 32 + rp;
        float2 mp = *reinterpret_cast<const float2*>(mb + mrow * 128 + 2 * col);

#pragma unroll
        for (int hsel = 0; hsel < 2; hsel++) {
            float m = hsel ? mp.y : mp.x;
            float e0 = hsel ? xa.z : xa.x, e1 = hsel ? xa.w : xa.y;
            float e2 = hsel ? xb.z : xb.x, e3 = hsel ? xb.w : xb.y;

            float om = 1.0f - m;
            float m2 = m * m, om2 = om * om;

            float sx = (e0 + e1) + (e2 + e3);
            float sq = fmaf(e0, e0, fmaf(e1, e1, fmaf(e2, e2, e3 * e3)));
            acc[0] = fmaf(sx, m, acc[0]);
            acc[1] = fmaf(sx * m, m2, acc[1]);
            acc[2] = fmaf(sq, m2 * m2, acc[2]);
            acc[3] = fmaf(sx, om, acc[3]);
            acc[4] = fmaf(sx * om, om2, acc[4]);
            acc[5] = fmaf(sq, om2 * om2, acc[5]);
        }
    }
}

__global__ __launch_bounds__(256) void k_reduce(const float4* __restrict__ x1,
                                                const float4* __restrict__ x2,
                                                const float* __restrict__ mask) {
    int bid  = blockIdx.x;
    int ch   = bid & (NCH - 1);
    int part = (bid >> 9) & (NPART - 1);
    int tensor = bid >> 11;           // 0 = x1, 1 = x2
    int b  = ch >> 7;
    const float4* p = (tensor ? x2 : x1) + (size_t)ch * (HW / 4) + part * 4096;
    const float*  mb = mask + b * MHW;
    int t = threadIdx.x;
    int lane = t & 31, wid = t >> 5;

    float acc[6];
#pragma unroll
    for (int i = 0; i < 6; i++) acc[i] = 0.f;

    // x1 batches 2-3: default policy (L2-resident for apply); else stream.
    if (tensor == 0 && b >= 2) reduce_body<false>(p, mb, part, t, acc);
    else                       reduce_body<true >(p, mb, part, t, acc);

    __shared__ float red[6][8];
#pragma unroll
    for (int i = 0; i < 6; i++) {
        float s = warpSum(acc[i]);
        if (lane == 0) red[i][wid] = s;
    }
    __syncthreads();
    if (wid == 0) {
#pragma unroll
        for (int i = 0; i < 6; i++) {
            float s = (lane < 8) ? red[i][lane] : 0.f;
            s = warpSum(s);
            if (lane == 0)
                g_sums[(size_t)(part * NCH + ch) * 12 + tensor * 6 + i] = s;
        }
    }
    __threadfence();
    __syncthreads();
    gdc_launch_dependents();
}

// ---------------------------------------------------------------------------
// Kernel 2 (R12 measured-good, unchanged): stats + modulation GEMVs.
// grid (BN, 16): 64 blocks, each owns 8 channels. PRE-WAIT: weight rows ->
// smem + mask sums. POST-WAIT: combine g_sums, stats, smem GEMV, coefs.
//   out = x1*(m^2*P + om^2*Q) + k1*m + k2*om
// ---------------------------------------------------------------------------
__global__ __launch_bounds__(256) void k_small(const float* __restrict__ mask,
                                               const float* __restrict__ w_in_mean,
                                               const float* __restrict__ w_in_var,
                                               const float* __restrict__ w_out_mean,
                                               const float* __restrict__ w_out_var) {
    int b  = blockIdx.x;
    int rg = blockIdx.y;              // 8-row group: rows [rg*8, rg*8+8)
    int t = threadIdx.x;
    int lane = t & 31, wid = t >> 5;

    __shared__ float w_sh[4][8][256]; // 32KB: [mat][local_row][j]
    __shared__ float ssum[CN * 12];
    __shared__ float v_sh[4 * 256];
    __shared__ float ada_sh[32];
    __shared__ float sred[2][8];
    __shared__ float sh_nin, sh_nout, sh_M2, sh_M2o;

    // ---- PRE-WAIT: weight prefetch ----
    {
        const float* wmats[4] = {w_in_mean, w_in_var, w_out_mean, w_out_var};
#pragma unroll
        for (int it = 0; it < 8; it++) {
            int id = t + it * 256;
            int mat = id >> 9;
            int rem = id & 511;
            int row = rem >> 6;
            int j4  = rem & 63;
            reinterpret_cast<float4*>(&w_sh[mat][row][0])[j4] =
                reinterpret_cast<const float4*>(wmats[mat] + (size_t)(rg * 8 + row) * 256)[j4];
        }
    }

    // ---- PRE-WAIT: mask sums (exact: 2x2-repeat upsample) ----
    const float* mb = mask + b * MHW;
    {
        float s1 = 0, s2 = 0;
        for (int i = t; i < MHW; i += 256) { float m = mb[i]; s1 += m; s2 += m * m; }
        s1 = warpSum(s1); s2 = warpSum(s2);
        if (lane == 0) { sred[0][wid] = s1; sred[1][wid] = s2; }
    }
    __syncthreads();
    if (t == 0) {
        float S1 = 0, S2 = 0;
        for (int i = 0; i < 8; i++) { S1 += sred[0][i]; S2 += sred[1][i]; }
        float msum = 4.f * S1, m2sum = 4.f * S2;
        sh_nin  = msum + EPS;
        sh_nout = ((float)HW - msum) + EPS;
        sh_M2   = m2sum;
        sh_M2o  = (float)HW - 2.f * msum + m2sum;
    }

    gdc_wait();

    for (int id = t; id < CN * 12; id += 256) {
        int c = id / 12, i = id - c * 12;
        float v = 0.f;
#pragma unroll
        for (int p = 0; p < NPART; p++)
            v += g_sums[(size_t)(p * NCH + b * CN + c) * 12 + i];
        ssum[id] = v;
    }
    __syncthreads();

    {
        int c = t & 127;
        int isx2 = t >> 7;
        const float* s = ssum + c * 12 + isx2 * 6;
        float A = s[0], Bb = s[1], Cc = s[2], Ao = s[3], Bo = s[4], Co = s[5];
        float mean_in = A / sh_nin;
        float var_in = (Cc - 2.f * mean_in * Bb + mean_in * mean_in * sh_M2) / sh_nin;
        var_in = fmaxf(var_in, 0.f);
        float mean_out = Ao / sh_nout;
        float var_out = (Co - 2.f * mean_out * Bo + mean_out * mean_out * sh_M2o) / sh_nout;
        var_out = fmaxf(var_out, 0.f);
        int vi = isx2 * 128 + c;
        v_sh[vi]       = mean_in;
        v_sh[256 + vi] = var_in;
        v_sh[512 + vi] = mean_out;
        v_sh[768 + vi] = var_out;
    }
    __syncthreads();

    {
#pragma unroll
        for (int it = 0; it < 4; it++) {
            int task = wid * 4 + it;
            int mat = task >> 3, lr = task & 7;
            const float* wrow = &w_sh[mat][lr][0];
            const float* vv = v_sh + mat * 256;
            float a = 0.f;
#pragma unroll
            for (int j = 0; j < 8; j++)
                a = fmaf(wrow[lane + 32 * j], vv[lane + 32 * j], a);
            a = warpSum(a);
            if (lane == 0) ada_sh[task] = a;
        }
    }
    __syncthreads();

    if (t < 8) {
        int c = rg * 8 + t;
        float mu_i = v_sh[c],       r_i = rsqrtf(v_sh[256 + c] + EPS);
        float mu_o = v_sh[512 + c], r_o = rsqrtf(v_sh[768 + c] + EPS);
        float P  = r_i * ada_sh[8 + t];
        float Q  = r_o * ada_sh[24 + t];
        float k1 = ada_sh[t]      - mu_i * P;
        float k2 = ada_sh[16 + t] - mu_o * Q;
        reinterpret_cast<float4*>(g_coef)[b * CN + c] = make_float4(P, Q, k1, k2);
    }
    __threadfence();
    __syncthreads();
    gdc_launch_dependents();
}

// ---------------------------------------------------------------------------
// Kernel 3: elementwise apply (R9 measured-good body), walking channels in
// REVERSE so it starts on the default-policy L2 lines (x1 batches 2-3)
// that k_reduce loaded most recently. PRE-WAIT: x1 + mask loads.
// out = x1*(m^2*P + om^2*Q) + k1*m + k2*om
// ---------------------------------------------------------------------------
__global__ __launch_bounds__(256) void k_apply(const float4* __restrict__ x1,
                                               const float* __restrict__ mask,
                                               float4* __restrict__ out) {
    int ch = (NCH - 1) - blockIdx.y;             // reverse channel walk
    int b = ch >> 7;
    const float* mb = mask + b * MHW;
    const float4* px = x1 + (size_t)ch * (HW / 4);
    float4* po = out + (size_t)ch * (HW / 4);
    int q0 = blockIdx.x * 512 + threadIdx.x;

    // pre-wait independent loads
    float4 v0 = px[q0];
    float4 v1 = px[q0 + 256];
    int mi0 = ((q0 >> 7) << 7) | ((2 * q0) & 126);
    int q1 = q0 + 256;
    int mi1 = ((q1 >> 7) << 7) | ((2 * q1) & 126);
    float2 mp0 = *reinterpret_cast<const float2*>(mb + mi0);
    float2 mp1 = *reinterpret_cast<const float2*>(mb + mi1);

    gdc_wait();

    float4 coef = __ldg(&reinterpret_cast<const float4*>(g_coef)[ch]);
    float P = coef.x, Q = coef.y, k1 = coef.z, k2 = coef.w;

#pragma unroll
    for (int r = 0; r < 2; r++) {
        int q = r ? q1 : q0;
        float4 v = r ? v1 : v0;
        float2 mp = r ? mp1 : mp0;
        float xs[4] = {v.x, v.y, v.z, v.w};
        float ms[4] = {mp.x, mp.x, mp.y, mp.y};
        float os[4];
#pragma unroll
        for (int i = 0; i < 4; i++) {
            float m = ms[i], om = 1.f - m;
            float s = m * m * P + om * om * Q;
            os[i] = xs[i] * s + k1 * m + k2 * om;
        }
        po[q] = make_float4(os[0], os[1], os[2], os[3]);
    }
}

extern "C" void kernel_launch(void* const* d_in, const int* in_sizes, int n_in,
                              void* d_out, int out_size) {
    const float* x1         = (const float*)d_in[0];
    const float* x2         = (const float*)d_in[1];
    const float* mask       = (const float*)d_in[2];
    const float* w_in_mean  = (const float*)d_in[3];
    const float* w_in_var   = (const float*)d_in[4];
    const float* w_out_mean = (const float*)d_in[5];
    const float* w_out_var  = (const float*)d_in[6];
    float* out = (float*)d_out;

    // 1) reduce — plain launch, tensor-split grid
    k_reduce<<<2 * NPART * NCH, 256>>>((const float4*)x1, (const float4*)x2, mask);

    // 2) stats+gemv — PDL consumer of reduce
    {
        cudaLaunchConfig_t cfg = {};
        cfg.gridDim = dim3(BN, 16);
        cfg.blockDim = dim3(256);
        cudaLaunchAttribute attr[1];
        attr[0].id = cudaLaunchAttributeProgrammaticStreamSerialization;
        attr[0].val.programmaticStreamSerializationAllowed = 1;
        cfg.attrs = attr;
        cfg.numAttrs = 1;
        cudaLaunchKernelEx(&cfg, k_small, mask, w_in_mean, w_in_var, w_out_mean, w_out_var);
    }

    // 3) apply — PDL consumer of k_small
    {
        cudaLaunchConfig_t cfg = {};
        cfg.gridDim = dim3(HW / 4 / 512, NCH);
        cfg.blockDim = dim3(256);
        cudaLaunchAttribute attr[1];
        attr[0].id = cudaLaunchAttributeProgrammaticStreamSerialization;
        attr[0].val.programmaticStreamSerializationAllowed = 1;
        cfg.attrs = attr;
        cfg.numAttrs = 1;
        cudaLaunchKernelEx(&cfg, k_apply, (const float4*)x1, mask, (float4*)out);
    }
}

// round 14
// speedup vs baseline: 1.2524x; 1.0007x over previous
#include <cuda_runtime.h>

#define EPS 1e-8f
#define BN 4
#define CN 128
#define HN 256
#define WN 256
#define HW (HN*WN)       // 65536
#define NCH (BN*CN)      // 512
#define MHW (128*128)    // 16384
#define NPART 4

// Scratch: per-channel partial sums (NPART parts) + final coefficients.
__device__ float g_sums[NPART * NCH * 12];
__device__ float g_coef[NCH * 4];          // per channel: P, Q, k1, k2

__device__ __forceinline__ float warpSum(float v) {
#pragma unroll
    for (int o = 16; o; o >>= 1) v += __shfl_xor_sync(0xffffffffu, v, o);
    return v;
}

__device__ __forceinline__ void gdc_wait() {
    asm volatile("griddepcontrol.wait;" ::: "memory");
}
__device__ __forceinline__ void gdc_launch_dependents() {
    asm volatile("griddepcontrol.launch_dependents;" ::: "memory");
}

// ---------------------------------------------------------------------------
// Kernel 1: per-(b,c) partial reductions, split by tensor.
// BID MAP REORDERED FOR L2 RESIDENCY: x2 occupies bids 0..2047 (streamed,
// runs first), x1 occupies bids 2048..4095 with BATCH-SEQUENTIAL layout so
// x1 batches 2-3 are the FINAL 1024 bids. Those load with DEFAULT policy
// (67MB fits L2) at the very end of the kernel — nothing streams after them
// to churn the sets; k_apply then reads them first (reverse walk).
//   A = Sum x*m, B = Sum x*m^3, C = Sum x^2*m^4  per region;
// mask 2x2-upsample factoring: sx=sum4(x), sq=sum4(x^2) per mask scalar.
// ---------------------------------------------------------------------------
template<bool STREAM>
__device__ __forceinline__ void reduce_body(const float4* __restrict__ p,
                                            const float* __restrict__ mb,
                                            int part, int t, float* acc) {
    int col = t & 63;
    int rpl0 = t >> 6;
#pragma unroll 1
    for (int k = 0; k < 8; k++) {
        int rp = k * 4 + rpl0;
        int q0 = rp * 128 + col;
        float4 xa = STREAM ? __ldcs(p + q0) : p[q0];
        float4 xb = STREAM ? __ldcs(p + q0 + 64) : p[q0 + 64];
        int mrow = part * 32 + rp;
        float2 mp = *reinterpret_cast<const float2*>(mb + mrow * 128 + 2 * col);

#pragma unroll
        for (int hsel = 0; hsel < 2; hsel++) {
            float m = hsel ? mp.y : mp.x;
            float e0 = hsel ? xa.z : xa.x, e1 = hsel ? xa.w : xa.y;
            float e2 = hsel ? xb.z : xb.x, e3 = hsel ? xb.w : xb.y;

            float om = 1.0f - m;
            float m2 = m * m, om2 = om * om;

            float sx = (e0 + e1) + (e2 + e3);
            float sq = fmaf(e0, e0, fmaf(e1, e1, fmaf(e2, e2, e3 * e3)));
            acc[0] = fmaf(sx, m, acc[0]);
            acc[1] = fmaf(sx * m, m2, acc[1]);
            acc[2] = fmaf(sq, m2 * m2, acc[2]);
            acc[3] = fmaf(sx, om, acc[3]);
            acc[4] = fmaf(sx * om, om2, acc[4]);
            acc[5] = fmaf(sq, om2 * om2, acc[5]);
        }
    }
}

__global__ __launch_bounds__(256) void k_reduce(const float4* __restrict__ x1,
                                                const float4* __restrict__ x2,
                                                const float* __restrict__ mask) {
    int bid  = blockIdx.x;
    int tensor, ch, part, b;
    if (bid < 2048) {
        // x2 half: runs first, fully streamed. ch-major/part layout.
        tensor = 1;
        ch = bid & (NCH - 1);
        part = bid >> 9;
        b = ch >> 7;
    } else {
        // x1 half: batch-SEQUENTIAL so batches 2-3 are the last 1024 bids.
        tensor = 0;
        int idx = bid - 2048;          // 0..2047
        b = idx >> 9;                  // 0..3 sequential
        part = (idx >> 7) & (NPART - 1);
        int c = idx & (CN - 1);
        ch = b * CN + c;
    }
    const float4* p = (tensor ? x2 : x1) + (size_t)ch * (HW / 4) + part * 4096;
    const float*  mb = mask + b * MHW;
    int t = threadIdx.x;
    int lane = t & 31, wid = t >> 5;

    float acc[6];
#pragma unroll
    for (int i = 0; i < 6; i++) acc[i] = 0.f;

    // x1 batches 2-3 (final bids): default policy -> survive into k_apply.
    if (tensor == 0 && b >= 2) reduce_body<false>(p, mb, part, t, acc);
    else                       reduce_body<true >(p, mb, part, t, acc);

    __shared__ float red[6][8];
#pragma unroll
    for (int i = 0; i < 6; i++) {
        float s = warpSum(acc[i]);
        if (lane == 0) red[i][wid] = s;
    }
    __syncthreads();
    if (wid == 0) {
#pragma unroll
        for (int i = 0; i < 6; i++) {
            float s = (lane < 8) ? red[i][lane] : 0.f;
            s = warpSum(s);
            if (lane == 0)
                g_sums[(size_t)(part * NCH + ch) * 12 + tensor * 6 + i] = s;
        }
    }
    __threadfence();
    __syncthreads();
    gdc_launch_dependents();
}

// ---------------------------------------------------------------------------
// Kernel 2 (R12 measured-good, unchanged): stats + modulation GEMVs.
// grid (BN, 16): 64 blocks, each owns 8 channels. PRE-WAIT: weight rows ->
// smem + mask sums. POST-WAIT: combine g_sums, stats, smem GEMV, coefs.
//   out = x1*(m^2*P + om^2*Q) + k1*m + k2*om
// ---------------------------------------------------------------------------
__global__ __launch_bounds__(256) void k_small(const float* __restrict__ mask,
                                               const float* __restrict__ w_in_mean,
                                               const float* __restrict__ w_in_var,
                                               const float* __restrict__ w_out_mean,
                                               const float* __restrict__ w_out_var) {
    int b  = blockIdx.x;
    int rg = blockIdx.y;              // 8-row group: rows [rg*8, rg*8+8)
    int t = threadIdx.x;
    int lane = t & 31, wid = t >> 5;

    __shared__ float w_sh[4][8][256]; // 32KB: [mat][local_row][j]
    __shared__ float ssum[CN * 12];
    __shared__ float v_sh[4 * 256];
    __shared__ float ada_sh[32];
    __shared__ float sred[2][8];
    __shared__ float sh_nin, sh_nout, sh_M2, sh_M2o;

    // ---- PRE-WAIT: weight prefetch ----
    {
        const float* wmats[4] = {w_in_mean, w_in_var, w_out_mean, w_out_var};
#pragma unroll
        for (int it = 0; it < 8; it++) {
            int id = t + it * 256;
            int mat = id >> 9;
            int rem = id & 511;
            int row = rem >> 6;
            int j4  = rem & 63;
            reinterpret_cast<float4*>(&w_sh[mat][row][0])[j4] =
                reinterpret_cast<const float4*>(wmats[mat] + (size_t)(rg * 8 + row) * 256)[j4];
        }
    }

    // ---- PRE-WAIT: mask sums (exact: 2x2-repeat upsample) ----
    const float* mb = mask + b * MHW;
    {
        float s1 = 0, s2 = 0;
        for (int i = t; i < MHW; i += 256) { float m = mb[i]; s1 += m; s2 += m * m; }
        s1 = warpSum(s1); s2 = warpSum(s2);
        if (lane == 0) { sred[0][wid] = s1; sred[1][wid] = s2; }
    }
    __syncthreads();
    if (t == 0) {
        float S1 = 0, S2 = 0;
        for (int i = 0; i < 8; i++) { S1 += sred[0][i]; S2 += sred[1][i]; }
        float msum = 4.f * S1, m2sum = 4.f * S2;
        sh_nin  = msum + EPS;
        sh_nout = ((float)HW - msum) + EPS;
        sh_M2   = m2sum;
        sh_M2o  = (float)HW - 2.f * msum + m2sum;
    }

    gdc_wait();

    for (int id = t; id < CN * 12; id += 256) {
        int c = id / 12, i = id - c * 12;
        float v = 0.f;
#pragma unroll
        for (int p = 0; p < NPART; p++)
            v += g_sums[(size_t)(p * NCH + b * CN + c) * 12 + i];
        ssum[id] = v;
    }
    __syncthreads();

    {
        int c = t & 127;
        int isx2 = t >> 7;
        const float* s = ssum + c * 12 + isx2 * 6;
        float A = s[0], Bb = s[1], Cc = s[2], Ao = s[3], Bo = s[4], Co = s[5];
        float mean_in = A / sh_nin;
        float var_in = (Cc - 2.f * mean_in * Bb + mean_in * mean_in * sh_M2) / sh_nin;
        var_in = fmaxf(var_in, 0.f);
        float mean_out = Ao / sh_nout;
        float var_out = (Co - 2.f * mean_out * Bo + mean_out * mean_out * sh_M2o) / sh_nout;
        var_out = fmaxf(var_out, 0.f);
        int vi = isx2 * 128 + c;
        v_sh[vi]       = mean_in;
        v_sh[256 + vi] = var_in;
        v_sh[512 + vi] = mean_out;
        v_sh[768 + vi] = var_out;
    }
    __syncthreads();

    {
#pragma unroll
        for (int it = 0; it < 4; it++) {
            int task = wid * 4 + it;
            int mat = task >> 3, lr = task & 7;
            const float* wrow = &w_sh[mat][lr][0];
            const float* vv = v_sh + mat * 256;
            float a = 0.f;
#pragma unroll
            for (int j = 0; j < 8; j++)
                a = fmaf(wrow[lane + 32 * j], vv[lane + 32 * j], a);
            a = warpSum(a);
            if (lane == 0) ada_sh[task] = a;
        }
    }
    __syncthreads();

    if (t < 8) {
        int c = rg * 8 + t;
        float mu_i = v_sh[c],       r_i = rsqrtf(v_sh[256 + c] + EPS);
        float mu_o = v_sh[512 + c], r_o = rsqrtf(v_sh[768 + c] + EPS);
        float P  = r_i * ada_sh[8 + t];
        float Q  = r_o * ada_sh[24 + t];
        float k1 = ada_sh[t]      - mu_i * P;
        float k2 = ada_sh[16 + t] - mu_o * Q;
        reinterpret_cast<float4*>(g_coef)[b * CN + c] = make_float4(P, Q, k1, k2);
    }
    __threadfence();
    __syncthreads();
    gdc_launch_dependents();
}

// ---------------------------------------------------------------------------
// Kernel 3: elementwise apply, reverse channel walk (reads the L2-resident
// x1 batches 3->2 first), __stcs output stores (evict-first: the 134MB of
// output writes must NOT churn the x1 residency). PRE-WAIT: x1+mask loads.
// out = x1*(m^2*P + om^2*Q) + k1*m + k2*om
// ---------------------------------------------------------------------------
__global__ __launch_bounds__(256) void k_apply(const float4* __restrict__ x1,
                                               const float* __restrict__ mask,
                                               float4* __restrict__ out) {
    int ch = (NCH - 1) - blockIdx.y;             // reverse channel walk
    int b = ch >> 7;
    const float* mb = mask + b * MHW;
    const float4* px = x1 + (size_t)ch * (HW / 4);
    float4* po = out + (size_t)ch * (HW / 4);
    int q0 = blockIdx.x * 512 + threadIdx.x;

    // pre-wait independent loads
    float4 v0 = px[q0];
    float4 v1 = px[q0 + 256];
    int mi0 = ((q0 >> 7) << 7) | ((2 * q0) & 126);
    int q1 = q0 + 256;
    int mi1 = ((q1 >> 7) << 7) | ((2 * q1) & 126);
    float2 mp0 = *reinterpret_cast<const float2*>(mb + mi0);
    float2 mp1 = *reinterpret_cast<const float2*>(mb + mi1);

    gdc_wait();

    float4 coef = __ldg(&reinterpret_cast<const float4*>(g_coef)[ch]);
    float P = coef.x, Q = coef.y, k1 = coef.z, k2 = coef.w;

#pragma unroll
    for (int r = 0; r < 2; r++) {
        int q = r ? q1 : q0;
        float4 v = r ? v1 : v0;
        float2 mp = r ? mp1 : mp0;
        float xs[4] = {v.x, v.y, v.z, v.w};
        float ms[4] = {mp.x, mp.x, mp.y, mp.y};
        float os[4];
#pragma unroll
        for (int i = 0; i < 4; i++) {
            float m = ms[i], om = 1.f - m;
            float s = m * m * P + om * om * Q;
            os[i] = xs[i] * s + k1 * m + k2 * om;
        }
        __stcs(po + q, make_float4(os[0], os[1], os[2], os[3]));
    }
}

extern "C" void kernel_launch(void* const* d_in, const int* in_sizes, int n_in,
                              void* d_out, int out_size) {
    const float* x1         = (const float*)d_in[0];
    const float* x2         = (const float*)d_in[1];
    const float* mask       = (const float*)d_in[2];
    const float* w_in_mean  = (const float*)d_in[3];
    const float* w_in_var   = (const float*)d_in[4];
    const float* w_out_mean = (const float*)d_in[5];
    const float* w_out_var  = (const float*)d_in[6];
    float* out = (float*)d_out;

    // 1) reduce — plain launch, residency-ordered tensor-split grid
    k_reduce<<<2 * NPART * NCH, 256>>>((const float4*)x1, (const float4*)x2, mask);

    // 2) stats+gemv — PDL consumer of reduce
    {
        cudaLaunchConfig_t cfg = {};
        cfg.gridDim = dim3(BN, 16);
        cfg.blockDim = dim3(256);
        cudaLaunchAttribute attr[1];
        attr[0].id = cudaLaunchAttributeProgrammaticStreamSerialization;
        attr[0].val.programmaticStreamSerializationAllowed = 1;
        cfg.attrs = attr;
        cfg.numAttrs = 1;
        cudaLaunchKernelEx(&cfg, k_small, mask, w_in_mean, w_in_var, w_out_mean, w_out_var);
    }

    // 3) apply — PDL consumer of k_small
    {
        cudaLaunchConfig_t cfg = {};
        cfg.gridDim = dim3(HW / 4 / 512, NCH);
        cfg.blockDim = dim3(256);
        cudaLaunchAttribute attr[1];
        attr[0].id = cudaLaunchAttributeProgrammaticStreamSerialization;
        attr[0].val.programmaticStreamSerializationAllowed = 1;
        cfg.attrs = attr;
        cfg.numAttrs = 1;
        cudaLaunchKernelEx(&cfg, k_apply, (const float4*)x1, mask, (float4*)out);
    }
}